// round 15
// baseline (speedup 1.0000x reference)
#include <cuda_runtime.h>
#include <cuda_fp16.h>
#include <cuda_bf16.h>
#include <mma.h>
#include <math.h>

using namespace nvcuda;

#define NN 50000
#define EE 800000
#define DD 128
#define ALPHAv 0.1f
#define SCH 512
#define SNCH ((NN + SCH - 1) / SCH)   // 98

// ---------------- device scratch ----------------
__device__ float g_h1[NN * DD];                                 // relu(h @ W_h + b), fp32
__device__ __align__(16) __half g_h1h[NN * DD];                 // fp16 shadow of h1
__device__ __align__(16) __half g_xs[2][2][(NN + 1) * DD];      // propagated features; row NN = zero pad
__device__ float g_z[2][NN * DD];                               // final APPNP output per metapath
__device__ int   g_deg_out[2][NN];
__device__ int   g_deg_in[2][NN];
__device__ float g_norm_s[2][NN];
__device__ float g_norm_d[2][NN];
__device__ int   g_rowoff[2][NN + 1];
__device__ int   g_cursor[2][NN];
__device__ int   g_csr_src[2][EE];
__device__ int   g_chsum[2][SNCH];
__device__ int   g_chbase[2][SNCH];
__device__ float g_wsum[2];

// ---------------- helpers ----------------
__device__ __forceinline__ float4 f4_fma(float s, float4 a, float4 b) {
    float4 r; r.x = s * a.x + b.x; r.y = s * a.y + b.y; r.z = s * a.z + b.z; r.w = s * a.w + b.w;
    return r;
}
__device__ __forceinline__ float htanh(float x) {
    float t;
    asm("tanh.approx.f32 %0, %1;" : "=f"(t) : "f"(x));
    return t;
}

// ---------------- zero / init ----------------
__global__ void k_zero() {
    int i = blockIdx.x * blockDim.x + threadIdx.x;
    if (i < NN) {
        g_deg_out[0][i] = 0; g_deg_out[1][i] = 0;
        g_deg_in[0][i]  = 0; g_deg_in[1][i]  = 0;
    }
    if (i < DD) {
        __half z = __float2half(0.f);
        g_xs[0][0][NN * DD + i] = z; g_xs[0][1][NN * DD + i] = z;
        g_xs[1][0][NN * DD + i] = z; g_xs[1][1][NN * DD + i] = z;
    }
    if (i < 2) g_wsum[i] = 0.f;
}

// ---------------- linear + relu: g_h1 = relu(h @ W + b); also fp16 shadow ----------------
__global__ __launch_bounds__(256) void k_linear(const float* __restrict__ h,
                                                const float* __restrict__ W,
                                                const float* __restrict__ b) {
    extern __shared__ float sm[];
    float* Ws = sm;               // DD*DD
    float* bs = Ws + DD * DD;     // DD
    float* rows = bs + DD;        // 8 warps * 8 * DD

    int tid = threadIdx.x, lane = tid & 31, wid = tid >> 5;
    for (int i = tid; i < DD * DD / 4; i += blockDim.x)
        ((float4*)Ws)[i] = ((const float4*)W)[i];
    if (tid < DD) bs[tid] = b[tid];
    __syncthreads();

    float* myrows = rows + wid * (8 * DD);
    float4 bf = *(float4*)&bs[lane * 4];
    int gw = blockIdx.x * 8 + wid;
    int nwarps = gridDim.x * 8;
    const int NT = NN / 8;   // 6250, exact

    for (int tile = gw; tile < NT; tile += nwarps) {
        __syncwarp();
        #pragma unroll
        for (int r = 0; r < 8; r++)
            *(float4*)&myrows[r * DD + lane * 4] =
                *(const float4*)&h[(size_t)(tile * 8 + r) * DD + lane * 4];
        __syncwarp();

        float4 acc[8];
        #pragma unroll
        for (int r = 0; r < 8; r++) acc[r] = bf;

        #pragma unroll 8
        for (int k = 0; k < DD; k += 4) {
            float4 w0 = *(float4*)&Ws[(k + 0) * DD + lane * 4];
            float4 w1 = *(float4*)&Ws[(k + 1) * DD + lane * 4];
            float4 w2 = *(float4*)&Ws[(k + 2) * DD + lane * 4];
            float4 w3 = *(float4*)&Ws[(k + 3) * DD + lane * 4];
            #pragma unroll
            for (int r = 0; r < 8; r++) {
                float4 hv = *(float4*)&myrows[r * DD + k];
                acc[r] = f4_fma(hv.x, w0, acc[r]);
                acc[r] = f4_fma(hv.y, w1, acc[r]);
                acc[r] = f4_fma(hv.z, w2, acc[r]);
                acc[r] = f4_fma(hv.w, w3, acc[r]);
            }
        }
        #pragma unroll
        for (int r = 0; r < 8; r++) {
            float4 o;
            o.x = fmaxf(acc[r].x, 0.f); o.y = fmaxf(acc[r].y, 0.f);
            o.z = fmaxf(acc[r].z, 0.f); o.w = fmaxf(acc[r].w, 0.f);
            size_t off = (size_t)(tile * 8 + r) * DD + lane * 4;
            *(float4*)&g_h1[off] = o;
            __half2 p0 = __floats2half2_rn(o.x, o.y);
            __half2 p1 = __floats2half2_rn(o.z, o.w);
            uint2 hw; hw.x = *(unsigned*)&p0; hw.y = *(unsigned*)&p1;
            *(uint2*)&g_h1h[off] = hw;
        }
    }
}

// ---------------- degree count (per graph, scalar: max atomic parallelism) ----------------
__global__ void k_count(const int* __restrict__ s, const int* __restrict__ d, int g) {
    int e = blockIdx.x * blockDim.x + threadIdx.x;
    if (e < EE) {
        atomicAdd(&g_deg_out[g][s[e]], 1);
        atomicAdd(&g_deg_in[g][d[e]], 1);
    }
}

// ---------------- scan1 + norms fused (per graph) ----------------
__global__ __launch_bounds__(SCH) void k_scan1(int g) {
    int c = blockIdx.x;
    int i = c * SCH + threadIdx.x;
    int v = 0;
    if (i < NN) {
        v = g_deg_in[g][i];
        int dout = g_deg_out[g][i]; if (dout < 1) dout = 1;
        int din = v < 1 ? 1 : v;
        g_norm_s[g][i] = rsqrtf((float)dout);
        g_norm_d[g][i] = rsqrtf((float)din);
    }
    __shared__ int ws[16];
    int lane = threadIdx.x & 31, wid = threadIdx.x >> 5;
    int sum = v;
    #pragma unroll
    for (int off = 16; off > 0; off >>= 1)
        sum += __shfl_xor_sync(0xffffffffu, sum, off);
    if (lane == 0) ws[wid] = sum;
    __syncthreads();
    if (wid == 0) {
        int s = (lane < 16) ? ws[lane] : 0;
        #pragma unroll
        for (int off = 8; off > 0; off >>= 1)
            s += __shfl_xor_sync(0xffffffffu, s, off);
        if (lane == 0) g_chsum[g][c] = s;
    }
}

__global__ void k_scan2(int g) {   // 1 warp
    int lane = threadIdx.x & 31;
    int carry = 0;
    for (int base = 0; base < SNCH; base += 32) {
        int idx = base + lane;
        int v = (idx < SNCH) ? g_chsum[g][idx] : 0;
        int x = v;
        #pragma unroll
        for (int off = 1; off < 32; off <<= 1) {
            int t = __shfl_up_sync(0xffffffffu, x, off);
            if (lane >= off) x += t;
        }
        if (idx < SNCH) g_chbase[g][idx] = carry + x - v;
        carry += __shfl_sync(0xffffffffu, x, 31);
    }
    if (lane == 0) g_rowoff[g][NN] = carry;   // == EE
}

__global__ __launch_bounds__(SCH) void k_scan3(int g) {
    int c = blockIdx.x;
    int i = c * SCH + threadIdx.x;
    int v = (i < NN) ? g_deg_in[g][i] : 0;
    __shared__ int ws[16];
    int lane = threadIdx.x & 31, wid = threadIdx.x >> 5;
    int x = v;
    #pragma unroll
    for (int off = 1; off < 32; off <<= 1) {
        int t = __shfl_up_sync(0xffffffffu, x, off);
        if (lane >= off) x += t;
    }
    if (lane == 31) ws[wid] = x;
    __syncthreads();
    if (wid == 0) {
        int y = (lane < 16) ? ws[lane] : 0;
        #pragma unroll
        for (int off = 1; off < 32; off <<= 1) {
            int t = __shfl_up_sync(0xffffffffu, y, off);
            if (lane >= off) y += t;
        }
        if (lane < 16) ws[lane] = y;
    }
    __syncthreads();
    int wb = wid ? ws[wid - 1] : 0;
    int excl = g_chbase[g][c] + wb + x - v;
    if (i < NN) { g_rowoff[g][i] = excl; g_cursor[g][i] = excl; }
}

// ---------------- fill CSR (per graph, scalar) ----------------
__global__ void k_fill(const int* __restrict__ s, const int* __restrict__ d, int g) {
    int e = blockIdx.x * blockDim.x + threadIdx.x;
    if (e < EE) {
        int slot = atomicAdd(&g_cursor[g][d[e]], 1);
        g_csr_src[g][slot] = s[e];
    }
}

// ---------------- initial scale: xs[g][0] = fp16(h1h * norm_s[g]) ----------------
__global__ void k_scale(int g) {
    int idx = blockIdx.x * blockDim.x + threadIdx.x;   // 4-element groups
    if (idx < NN * DD / 4) {
        int node = idx >> 5;
        float ns = g_norm_s[g][node];
        uint2 raw = *(const uint2*)&g_h1h[(size_t)idx * 4];
        float2 f0 = __half22float2(*(__half2*)&raw.x);
        float2 f1 = __half22float2(*(__half2*)&raw.y);
        __half2 o0 = __floats2half2_rn(f0.x * ns, f0.y * ns);
        __half2 o1 = __floats2half2_rn(f1.x * ns, f1.y * ns);
        uint2 w; w.x = *(unsigned*)&o0; w.y = *(unsigned*)&o1;
        *(uint2*)&g_xs[g][0][(size_t)idx * 4] = w;
    }
}

// ---------------- APPNP aggregation: warp per dst node, 16-edge batches (MLP=8) ----------------
__global__ __launch_bounds__(256) void k_agg(int g, int pp, int last) {
    int lane = threadIdx.x & 31, wid = threadIdx.x >> 5;
    int node = blockIdx.x * 8 + wid;
    if (node >= NN) return;

    const __half* __restrict__ xin = g_xs[g][pp];
    const int* __restrict__ csr = g_csr_src[g];
    int ro = g_rowoff[g][node], re = g_rowoff[g][node + 1];

    int half_ = lane >> 4;          // which row of each pair this lane loads
    int sub = lane & 15;            // 16-byte column slice

    float acc[8];
    #pragma unroll
    for (int i = 0; i < 8; i++) acc[i] = 0.f;

    for (int base = ro; base < re; base += 32) {
        int e = base + lane;
        int s = (e < re) ? csr[e] : NN;      // NN = zero pad row
        int cnt = re - base; if (cnt > 32) cnt = 32;
        int cr = (cnt + 15) & ~15;
        for (int j = 0; j < cr; j += 16) {
            int rsel[8];
            #pragma unroll
            for (int k2 = 0; k2 < 8; k2++) {
                int rA = __shfl_sync(0xffffffffu, s, j + 2 * k2);
                int rB = __shfl_sync(0xffffffffu, s, j + 2 * k2 + 1);
                rsel[k2] = half_ ? rB : rA;
            }
            uint4 v[8];
            #pragma unroll
            for (int k2 = 0; k2 < 8; k2++)
                v[k2] = *(const uint4*)&xin[(size_t)rsel[k2] * DD + sub * 8];
            #pragma unroll
            for (int k2 = 0; k2 < 8; k2++) {
                float2 f0 = __half22float2(*(__half2*)&v[k2].x);
                float2 f1 = __half22float2(*(__half2*)&v[k2].y);
                float2 f2 = __half22float2(*(__half2*)&v[k2].z);
                float2 f3 = __half22float2(*(__half2*)&v[k2].w);
                acc[0] += f0.x; acc[1] += f0.y; acc[2] += f1.x; acc[3] += f1.y;
                acc[4] += f2.x; acc[5] += f2.y; acc[6] += f3.x; acc[7] += f3.y;
            }
        }
    }

    #pragma unroll
    for (int i = 0; i < 8; i++)
        acc[i] += __shfl_xor_sync(0xffffffffu, acc[i], 16);

    float c = (1.f - ALPHAv) * g_norm_d[g][node];
    uint4 h0raw = *(const uint4*)&g_h1h[(size_t)node * DD + sub * 8];
    float2 h0a = __half22float2(*(__half2*)&h0raw.x);
    float2 h0b = __half22float2(*(__half2*)&h0raw.y);
    float2 h0c = __half22float2(*(__half2*)&h0raw.z);
    float2 h0d = __half22float2(*(__half2*)&h0raw.w);
    float v8[8];
    v8[0] = c * acc[0] + ALPHAv * h0a.x; v8[1] = c * acc[1] + ALPHAv * h0a.y;
    v8[2] = c * acc[2] + ALPHAv * h0b.x; v8[3] = c * acc[3] + ALPHAv * h0b.y;
    v8[4] = c * acc[4] + ALPHAv * h0c.x; v8[5] = c * acc[5] + ALPHAv * h0c.y;
    v8[6] = c * acc[6] + ALPHAv * h0d.x; v8[7] = c * acc[7] + ALPHAv * h0d.y;

    if (last) {
        float4 o;
        o.x = v8[half_ * 4 + 0]; o.y = v8[half_ * 4 + 1];
        o.z = v8[half_ * 4 + 2]; o.w = v8[half_ * 4 + 3];
        *(float4*)&g_z[g][(size_t)node * DD + sub * 8 + half_ * 4] = o;
    } else {
        float ns = g_norm_s[g][node];
        __half2 o0 = __floats2half2_rn(v8[half_ * 4 + 0] * ns, v8[half_ * 4 + 1] * ns);
        __half2 o1 = __floats2half2_rn(v8[half_ * 4 + 2] * ns, v8[half_ * 4 + 3] * ns);
        uint2 w; w.x = *(unsigned*)&o0; w.y = *(unsigned*)&o1;
        *(uint2*)&g_xs[g][1 - pp][(size_t)node * DD + sub * 8 + half_ * 4] = w;
    }
}

// ---------------- attention scores via bf16 WMMA tensor cores (per graph) ----------------
#define ATT_TILES (NN / 16)   // 3125, exact

__global__ __launch_bounds__(256) void k_att(const float* __restrict__ W,
                                             const float* __restrict__ b,
                                             const float* __restrict__ q, int p) {
    extern __shared__ char smraw[];
    __nv_bfloat16* Wb = (__nv_bfloat16*)smraw;                    // 128*128 bf16 = 32KB
    float* bs = (float*)(smraw + DD * DD * 2);                    // 128 f
    float* qs = bs + DD;                                          // 128 f
    __nv_bfloat16* zt = (__nv_bfloat16*)(qs + DD);                // 8 warps * 16*128 bf16 = 32KB
    float* scr = (float*)(zt + 8 * 16 * DD);                      // 8 warps * 256 f = 8KB
    __shared__ float red[8];

    const float* __restrict__ zin = g_z[p];
    int tid = threadIdx.x, lane = tid & 31, wid = tid >> 5;

    for (int i = tid; i < DD * DD; i += 256)
        Wb[i] = __float2bfloat16(W[i]);
    if (tid < DD) { bs[tid] = b[tid]; qs[tid] = q[tid]; }
    __syncthreads();

    float wsum_local = 0.f;
    int tile = blockIdx.x * 8 + wid;

    if (tile < ATT_TILES) {
        __nv_bfloat16* myz = zt + wid * (16 * DD);
        float* myscr = scr + wid * 256;

        #pragma unroll
        for (int j = 0; j < 16; j++) {
            int idx = j * 32 + lane;
            int row = idx >> 5, c4 = idx & 31;
            float4 v = *(const float4*)&zin[(size_t)(tile * 16 + row) * DD + c4 * 4];
            __nv_bfloat162* dst = (__nv_bfloat162*)&myz[row * DD + c4 * 4];
            dst[0] = __floats2bfloat162_rn(v.x, v.y);
            dst[1] = __floats2bfloat162_rn(v.z, v.w);
        }
        __syncwarp();

        wmma::fragment<wmma::accumulator, 16, 16, 16, float> accf[8];
        #pragma unroll
        for (int n = 0; n < 8; n++) wmma::fill_fragment(accf[n], 0.f);

        #pragma unroll
        for (int k = 0; k < 8; k++) {
            wmma::fragment<wmma::matrix_a, 16, 16, 16, __nv_bfloat16, wmma::row_major> af;
            wmma::load_matrix_sync(af, myz + k * 16, DD);
            #pragma unroll
            for (int n = 0; n < 8; n++) {
                wmma::fragment<wmma::matrix_b, 16, 16, 16, __nv_bfloat16, wmma::row_major> bfg;
                wmma::load_matrix_sync(bfg, Wb + (k * 16) * DD + n * 16, DD);
                wmma::mma_sync(accf[n], af, bfg, accf[n]);
            }
        }

        #pragma unroll
        for (int n = 0; n < 8; n++) {
            wmma::store_matrix_sync(myscr, accf[n], 16, wmma::mem_row_major);
            __syncwarp();
            #pragma unroll
            for (int i = 0; i < 8; i++) {
                int e = i * 32 + lane;
                int col = n * 16 + (e & 15);
                wsum_local += htanh(myscr[e] + bs[col]) * qs[col];
            }
            __syncwarp();
        }
    }

    #pragma unroll
    for (int off = 16; off > 0; off >>= 1)
        wsum_local += __shfl_xor_sync(0xffffffffu, wsum_local, off);
    if (lane == 0) red[wid] = wsum_local;
    __syncthreads();
    if (tid == 0) {
        float s = 0.f;
        #pragma unroll
        for (int i = 0; i < 8; i++) s += red[i];
        atomicAdd(&g_wsum[p], s);
    }
}

// ---------------- softmax(beta) + combine ----------------
__global__ void k_combine(float* __restrict__ out) {
    int idx = blockIdx.x * blockDim.x + threadIdx.x;
    if (idx < NN * DD / 4) {
        float w0 = g_wsum[0] / (float)NN;
        float w1 = g_wsum[1] / (float)NN;
        float m = fmaxf(w0, w1);
        float e0 = expf(w0 - m), e1 = expf(w1 - m);
        float inv = 1.f / (e0 + e1);
        float b0 = e0 * inv, b1 = e1 * inv;
        float4 z0 = ((const float4*)g_z[0])[idx];
        float4 z1 = ((const float4*)g_z[1])[idx];
        float4 o;
        o.x = b0 * z0.x + b1 * z1.x;
        o.y = b0 * z0.y + b1 * z1.y;
        o.z = b0 * z0.z + b1 * z1.z;
        o.w = b0 * z0.w + b1 * z1.w;
        ((float4*)out)[idx] = o;
    }
}

// ---------------- launch (R14 topology, verbatim) ----------------
extern "C" void kernel_launch(void* const* d_in, const int* in_sizes, int n_in,
                              void* d_out, int out_size) {
    const float* h     = (const float*)d_in[0];
    const int*   src0  = (const int*)d_in[1];
    const int*   dst0  = (const int*)d_in[2];
    const int*   src1  = (const int*)d_in[3];
    const int*   dst1  = (const int*)d_in[4];
    const float* W_h   = (const float*)d_in[5];
    const float* b_h   = (const float*)d_in[6];
    const float* W_att = (const float*)d_in[7];
    const float* b_att = (const float*)d_in[8];
    const float* q_att = (const float*)d_in[9];
    float* out = (float*)d_out;

    static cudaStream_t sB = nullptr, sC = nullptr;
    static cudaEvent_t evZ = nullptr, evLin = nullptr, evB = nullptr, evC = nullptr;
    static bool init_done = false;

    size_t smemGemm = (size_t)(DD * DD + DD + 8 * 8 * DD) * sizeof(float);
    size_t smemAtt  = (size_t)(DD * DD * 2) + (size_t)(2 * DD) * sizeof(float)
                    + (size_t)(8 * 16 * DD * 2) + (size_t)(8 * 256) * sizeof(float);

    if (!init_done) {
        cudaFuncSetAttribute(k_linear, cudaFuncAttributeMaxDynamicSharedMemorySize, (int)smemGemm);
        cudaFuncSetAttribute(k_att,    cudaFuncAttributeMaxDynamicSharedMemorySize, (int)smemAtt);
        cudaStreamCreateWithFlags(&sB, cudaStreamNonBlocking);
        cudaStreamCreateWithFlags(&sC, cudaStreamNonBlocking);
        cudaEventCreateWithFlags(&evZ, cudaEventDisableTiming);
        cudaEventCreateWithFlags(&evLin, cudaEventDisableTiming);
        cudaEventCreateWithFlags(&evB, cudaEventDisableTiming);
        cudaEventCreateWithFlags(&evC, cudaEventDisableTiming);
        init_done = true;
    }

    dim3 gE((EE + 255) / 256);
    dim3 gS((NN * DD / 4 + 255) / 256);
    dim3 gA(NN / 8);
    dim3 gAtt((ATT_TILES + 7) / 8);

    // ---- stream 0 (capture origin): linear first ----
    k_linear<<<304, 256, smemGemm>>>(h, W_h, b_h);
    cudaEventRecord(evLin, 0);

    // ---- stream B: zero, then graph 1 CSR chain ----
    k_zero<<<(NN + 255) / 256, 256, 0, sB>>>();
    cudaEventRecord(evZ, sB);

    k_count<<<gE, 256, 0, sB>>>(src1, dst1, 1);
    k_scan1<<<SNCH, SCH, 0, sB>>>(1);
    k_scan2<<<1, 32, 0, sB>>>(1);
    k_scan3<<<SNCH, SCH, 0, sB>>>(1);
    k_fill<<<gE, 256, 0, sB>>>(src1, dst1, 1);

    // ---- stream C: graph 0 CSR chain (waits only on zero) ----
    cudaStreamWaitEvent(sC, evZ, 0);
    k_count<<<gE, 256, 0, sC>>>(src0, dst0, 0);
    k_scan1<<<SNCH, SCH, 0, sC>>>(0);
    k_scan2<<<1, 32, 0, sC>>>(0);
    k_scan3<<<SNCH, SCH, 0, sC>>>(0);
    k_fill<<<gE, 256, 0, sC>>>(src0, dst0, 0);

    // ---- stream C: graph 0 propagation (needs linear) ----
    cudaStreamWaitEvent(sC, evLin, 0);
    k_scale<<<gS, 256, 0, sC>>>(0);
    k_agg<<<gA, 256, 0, sC>>>(0, 0, 0);
    k_agg<<<gA, 256, 0, sC>>>(0, 1, 0);
    k_agg<<<gA, 256, 0, sC>>>(0, 0, 1);
    k_att<<<gAtt, 256, smemAtt, sC>>>(W_att, b_att, q_att, 0);
    cudaEventRecord(evC, sC);

    // ---- stream B: graph 1 propagation (needs linear) ----
    cudaStreamWaitEvent(sB, evLin, 0);
    k_scale<<<gS, 256, 0, sB>>>(1);
    k_agg<<<gA, 256, 0, sB>>>(1, 0, 0);
    k_agg<<<gA, 256, 0, sB>>>(1, 1, 0);
    k_agg<<<gA, 256, 0, sB>>>(1, 0, 1);
    k_att<<<gAtt, 256, smemAtt, sB>>>(W_att, b_att, q_att, 1);
    cudaEventRecord(evB, sB);

    // ---- join + combine on origin ----
    cudaStreamWaitEvent(0, evB, 0);
    cudaStreamWaitEvent(0, evC, 0);
    k_combine<<<(NN * DD / 4 + 255) / 256, 256>>>(out);
}

// round 16
// speedup vs baseline: 1.0899x; 1.0899x over previous
#include <cuda_runtime.h>
#include <cuda_fp16.h>
#include <cuda_bf16.h>
#include <mma.h>
#include <math.h>

using namespace nvcuda;

#define NN 50000
#define EE 800000
#define DD 128
#define ALPHAv 0.1f
#define SCH 512
#define SNCH ((NN + SCH - 1) / SCH)   // 98

// ---------------- device scratch ----------------
__device__ float g_h1[NN * DD];                                 // relu(h @ W_h + b), fp32
__device__ __align__(16) __half g_h1h[NN * DD];                 // fp16 shadow of h1
__device__ __align__(16) __half g_xs[2][2][(NN + 1) * DD];      // propagated features; row NN = zero pad
__device__ float g_z[2][NN * DD];                               // final APPNP output per metapath
__device__ int   g_deg_out[2][NN];
__device__ int   g_deg_in[2][NN];
__device__ float g_norm_s[2][NN];
__device__ float g_norm_d[2][NN];
__device__ int   g_rowoff[2][NN + 1];
__device__ int   g_cursor[2][NN];
__device__ int   g_csr_src[2][EE];
__device__ int   g_chsum[2][SNCH];
__device__ int   g_chbase[2][SNCH];
__device__ float g_wsum[2];

// ---------------- helpers ----------------
__device__ __forceinline__ float4 f4_fma(float s, float4 a, float4 b) {
    float4 r; r.x = s * a.x + b.x; r.y = s * a.y + b.y; r.z = s * a.z + b.z; r.w = s * a.w + b.w;
    return r;
}
__device__ __forceinline__ float htanh(float x) {
    float t;
    asm("tanh.approx.f32 %0, %1;" : "=f"(t) : "f"(x));
    return t;
}

// ---------------- zero / init ----------------
__global__ void k_zero() {
    int i = blockIdx.x * blockDim.x + threadIdx.x;
    if (i < NN) {
        g_deg_out[0][i] = 0; g_deg_out[1][i] = 0;
        g_deg_in[0][i]  = 0; g_deg_in[1][i]  = 0;
    }
    if (i < DD) {
        __half z = __float2half(0.f);
        g_xs[0][0][NN * DD + i] = z; g_xs[0][1][NN * DD + i] = z;
        g_xs[1][0][NN * DD + i] = z; g_xs[1][1][NN * DD + i] = z;
    }
    if (i < 2) g_wsum[i] = 0.f;
}

// ---------------- linear + relu: g_h1 = relu(h @ W + b); also fp16 shadow ----------------
__global__ __launch_bounds__(256) void k_linear(const float* __restrict__ h,
                                                const float* __restrict__ W,
                                                const float* __restrict__ b) {
    extern __shared__ float sm[];
    float* Ws = sm;               // DD*DD
    float* bs = Ws + DD * DD;     // DD
    float* rows = bs + DD;        // 8 warps * 8 * DD

    int tid = threadIdx.x, lane = tid & 31, wid = tid >> 5;
    for (int i = tid; i < DD * DD / 4; i += blockDim.x)
        ((float4*)Ws)[i] = ((const float4*)W)[i];
    if (tid < DD) bs[tid] = b[tid];
    __syncthreads();

    float* myrows = rows + wid * (8 * DD);
    float4 bf = *(float4*)&bs[lane * 4];
    int gw = blockIdx.x * 8 + wid;
    int nwarps = gridDim.x * 8;
    const int NT = NN / 8;   // 6250, exact

    for (int tile = gw; tile < NT; tile += nwarps) {
        __syncwarp();
        #pragma unroll
        for (int r = 0; r < 8; r++)
            *(float4*)&myrows[r * DD + lane * 4] =
                *(const float4*)&h[(size_t)(tile * 8 + r) * DD + lane * 4];
        __syncwarp();

        float4 acc[8];
        #pragma unroll
        for (int r = 0; r < 8; r++) acc[r] = bf;

        #pragma unroll 8
        for (int k = 0; k < DD; k += 4) {
            float4 w0 = *(float4*)&Ws[(k + 0) * DD + lane * 4];
            float4 w1 = *(float4*)&Ws[(k + 1) * DD + lane * 4];
            float4 w2 = *(float4*)&Ws[(k + 2) * DD + lane * 4];
            float4 w3 = *(float4*)&Ws[(k + 3) * DD + lane * 4];
            #pragma unroll
            for (int r = 0; r < 8; r++) {
                float4 hv = *(float4*)&myrows[r * DD + k];
                acc[r] = f4_fma(hv.x, w0, acc[r]);
                acc[r] = f4_fma(hv.y, w1, acc[r]);
                acc[r] = f4_fma(hv.z, w2, acc[r]);
                acc[r] = f4_fma(hv.w, w3, acc[r]);
            }
        }
        #pragma unroll
        for (int r = 0; r < 8; r++) {
            float4 o;
            o.x = fmaxf(acc[r].x, 0.f); o.y = fmaxf(acc[r].y, 0.f);
            o.z = fmaxf(acc[r].z, 0.f); o.w = fmaxf(acc[r].w, 0.f);
            size_t off = (size_t)(tile * 8 + r) * DD + lane * 4;
            *(float4*)&g_h1[off] = o;
            __half2 p0 = __floats2half2_rn(o.x, o.y);
            __half2 p1 = __floats2half2_rn(o.z, o.w);
            uint2 hw; hw.x = *(unsigned*)&p0; hw.y = *(unsigned*)&p1;
            *(uint2*)&g_h1h[off] = hw;
        }
    }
}

// ---------------- degree count (per graph, scalar: max atomic parallelism) ----------------
__global__ void k_count(const int* __restrict__ s, const int* __restrict__ d, int g) {
    int e = blockIdx.x * blockDim.x + threadIdx.x;
    if (e < EE) {
        atomicAdd(&g_deg_out[g][s[e]], 1);
        atomicAdd(&g_deg_in[g][d[e]], 1);
    }
}

// ---------------- scan1 + norms fused (per graph) ----------------
__global__ __launch_bounds__(SCH) void k_scan1(int g) {
    int c = blockIdx.x;
    int i = c * SCH + threadIdx.x;
    int v = 0;
    if (i < NN) {
        v = g_deg_in[g][i];
        int dout = g_deg_out[g][i]; if (dout < 1) dout = 1;
        int din = v < 1 ? 1 : v;
        g_norm_s[g][i] = rsqrtf((float)dout);
        g_norm_d[g][i] = rsqrtf((float)din);
    }
    __shared__ int ws[16];
    int lane = threadIdx.x & 31, wid = threadIdx.x >> 5;
    int sum = v;
    #pragma unroll
    for (int off = 16; off > 0; off >>= 1)
        sum += __shfl_xor_sync(0xffffffffu, sum, off);
    if (lane == 0) ws[wid] = sum;
    __syncthreads();
    if (wid == 0) {
        int s = (lane < 16) ? ws[lane] : 0;
        #pragma unroll
        for (int off = 8; off > 0; off >>= 1)
            s += __shfl_xor_sync(0xffffffffu, s, off);
        if (lane == 0) g_chsum[g][c] = s;
    }
}

__global__ void k_scan2(int g) {   // 1 warp
    int lane = threadIdx.x & 31;
    int carry = 0;
    for (int base = 0; base < SNCH; base += 32) {
        int idx = base + lane;
        int v = (idx < SNCH) ? g_chsum[g][idx] : 0;
        int x = v;
        #pragma unroll
        for (int off = 1; off < 32; off <<= 1) {
            int t = __shfl_up_sync(0xffffffffu, x, off);
            if (lane >= off) x += t;
        }
        if (idx < SNCH) g_chbase[g][idx] = carry + x - v;
        carry += __shfl_sync(0xffffffffu, x, 31);
    }
    if (lane == 0) g_rowoff[g][NN] = carry;   // == EE
}

__global__ __launch_bounds__(SCH) void k_scan3(int g) {
    int c = blockIdx.x;
    int i = c * SCH + threadIdx.x;
    int v = (i < NN) ? g_deg_in[g][i] : 0;
    __shared__ int ws[16];
    int lane = threadIdx.x & 31, wid = threadIdx.x >> 5;
    int x = v;
    #pragma unroll
    for (int off = 1; off < 32; off <<= 1) {
        int t = __shfl_up_sync(0xffffffffu, x, off);
        if (lane >= off) x += t;
    }
    if (lane == 31) ws[wid] = x;
    __syncthreads();
    if (wid == 0) {
        int y = (lane < 16) ? ws[lane] : 0;
        #pragma unroll
        for (int off = 1; off < 32; off <<= 1) {
            int t = __shfl_up_sync(0xffffffffu, y, off);
            if (lane >= off) y += t;
        }
        if (lane < 16) ws[lane] = y;
    }
    __syncthreads();
    int wb = wid ? ws[wid - 1] : 0;
    int excl = g_chbase[g][c] + wb + x - v;
    if (i < NN) { g_rowoff[g][i] = excl; g_cursor[g][i] = excl; }
}

// ---------------- fill CSR (per graph, scalar) ----------------
__global__ void k_fill(const int* __restrict__ s, const int* __restrict__ d, int g) {
    int e = blockIdx.x * blockDim.x + threadIdx.x;
    if (e < EE) {
        int slot = atomicAdd(&g_cursor[g][d[e]], 1);
        g_csr_src[g][slot] = s[e];
    }
}

// ---------------- APPNP aggregation: warp per dst node, float4 paired-row gathers ----------------
// first=1: gather h1h and apply norm_s[src] in fp32 (replaces k_scale entirely).
__global__ __launch_bounds__(256) void k_agg(int g, int pp, int first, int last) {
    int lane = threadIdx.x & 31, wid = threadIdx.x >> 5;
    int node = blockIdx.x * 8 + wid;
    if (node >= NN) return;

    const __half* __restrict__ xin = first ? g_h1h : g_xs[g][pp];
    const int* __restrict__ csr = g_csr_src[g];
    const float* __restrict__ nsrc = g_norm_s[g];
    int ro = g_rowoff[g][node], re = g_rowoff[g][node + 1];

    int half_ = lane >> 4;          // which row of each pair this lane loads
    int sub = lane & 15;            // 16-byte column slice

    float acc[8];
    #pragma unroll
    for (int i = 0; i < 8; i++) acc[i] = 0.f;

    if (first) {
        for (int base = ro; base < re; base += 32) {
            int e = base + lane;
            int s = (e < re) ? csr[e] : 0;                // pad -> row 0 (valid data)
            float nm = (e < re) ? nsrc[s] : 0.f;          // pad -> weight 0
            int cnt = re - base; if (cnt > 32) cnt = 32;
            int cr = (cnt + 7) & ~7;
            for (int j = 0; j < cr; j += 8) {
                int rsel[4]; float msel[4];
                #pragma unroll
                for (int k2 = 0; k2 < 4; k2++) {
                    int rA = __shfl_sync(0xffffffffu, s, j + 2 * k2);
                    int rB = __shfl_sync(0xffffffffu, s, j + 2 * k2 + 1);
                    float mA = __shfl_sync(0xffffffffu, nm, j + 2 * k2);
                    float mB = __shfl_sync(0xffffffffu, nm, j + 2 * k2 + 1);
                    rsel[k2] = half_ ? rB : rA;
                    msel[k2] = half_ ? mB : mA;
                }
                uint4 v[4];
                #pragma unroll
                for (int k2 = 0; k2 < 4; k2++)
                    v[k2] = *(const uint4*)&xin[(size_t)rsel[k2] * DD + sub * 8];
                #pragma unroll
                for (int k2 = 0; k2 < 4; k2++) {
                    float m = msel[k2];
                    float2 f0 = __half22float2(*(__half2*)&v[k2].x);
                    float2 f1 = __half22float2(*(__half2*)&v[k2].y);
                    float2 f2 = __half22float2(*(__half2*)&v[k2].z);
                    float2 f3 = __half22float2(*(__half2*)&v[k2].w);
                    acc[0] = fmaf(f0.x, m, acc[0]); acc[1] = fmaf(f0.y, m, acc[1]);
                    acc[2] = fmaf(f1.x, m, acc[2]); acc[3] = fmaf(f1.y, m, acc[3]);
                    acc[4] = fmaf(f2.x, m, acc[4]); acc[5] = fmaf(f2.y, m, acc[5]);
                    acc[6] = fmaf(f3.x, m, acc[6]); acc[7] = fmaf(f3.y, m, acc[7]);
                }
            }
        }
    } else {
        for (int base = ro; base < re; base += 32) {
            int e = base + lane;
            int s = (e < re) ? csr[e] : NN;      // NN = zero pad row
            int cnt = re - base; if (cnt > 32) cnt = 32;
            int cr = (cnt + 7) & ~7;
            for (int j = 0; j < cr; j += 8) {
                int rsel[4];
                #pragma unroll
                for (int k2 = 0; k2 < 4; k2++) {
                    int rA = __shfl_sync(0xffffffffu, s, j + 2 * k2);
                    int rB = __shfl_sync(0xffffffffu, s, j + 2 * k2 + 1);
                    rsel[k2] = half_ ? rB : rA;
                }
                uint4 v[4];
                #pragma unroll
                for (int k2 = 0; k2 < 4; k2++)
                    v[k2] = *(const uint4*)&xin[(size_t)rsel[k2] * DD + sub * 8];
                #pragma unroll
                for (int k2 = 0; k2 < 4; k2++) {
                    float2 f0 = __half22float2(*(__half2*)&v[k2].x);
                    float2 f1 = __half22float2(*(__half2*)&v[k2].y);
                    float2 f2 = __half22float2(*(__half2*)&v[k2].z);
                    float2 f3 = __half22float2(*(__half2*)&v[k2].w);
                    acc[0] += f0.x; acc[1] += f0.y; acc[2] += f1.x; acc[3] += f1.y;
                    acc[4] += f2.x; acc[5] += f2.y; acc[6] += f3.x; acc[7] += f3.y;
                }
            }
        }
    }

    #pragma unroll
    for (int i = 0; i < 8; i++)
        acc[i] += __shfl_xor_sync(0xffffffffu, acc[i], 16);

    float c = (1.f - ALPHAv) * g_norm_d[g][node];
    uint4 h0raw = *(const uint4*)&g_h1h[(size_t)node * DD + sub * 8];
    float2 h0a = __half22float2(*(__half2*)&h0raw.x);
    float2 h0b = __half22float2(*(__half2*)&h0raw.y);
    float2 h0c = __half22float2(*(__half2*)&h0raw.z);
    float2 h0d = __half22float2(*(__half2*)&h0raw.w);
    float v8[8];
    v8[0] = c * acc[0] + ALPHAv * h0a.x; v8[1] = c * acc[1] + ALPHAv * h0a.y;
    v8[2] = c * acc[2] + ALPHAv * h0b.x; v8[3] = c * acc[3] + ALPHAv * h0b.y;
    v8[4] = c * acc[4] + ALPHAv * h0c.x; v8[5] = c * acc[5] + ALPHAv * h0c.y;
    v8[6] = c * acc[6] + ALPHAv * h0d.x; v8[7] = c * acc[7] + ALPHAv * h0d.y;

    if (last) {
        float4 o;
        o.x = v8[half_ * 4 + 0]; o.y = v8[half_ * 4 + 1];
        o.z = v8[half_ * 4 + 2]; o.w = v8[half_ * 4 + 3];
        *(float4*)&g_z[g][(size_t)node * DD + sub * 8 + half_ * 4] = o;
    } else {
        float ns = g_norm_s[g][node];
        __half2 o0 = __floats2half2_rn(v8[half_ * 4 + 0] * ns, v8[half_ * 4 + 1] * ns);
        __half2 o1 = __floats2half2_rn(v8[half_ * 4 + 2] * ns, v8[half_ * 4 + 3] * ns);
        uint2 w; w.x = *(unsigned*)&o0; w.y = *(unsigned*)&o1;
        *(uint2*)&g_xs[g][1 - pp][(size_t)node * DD + sub * 8 + half_ * 4] = w;
    }
}

// ---------------- attention scores via bf16 WMMA tensor cores (per graph) ----------------
#define ATT_TILES (NN / 16)   // 3125, exact

__global__ __launch_bounds__(256) void k_att(const float* __restrict__ W,
                                             const float* __restrict__ b,
                                             const float* __restrict__ q, int p) {
    extern __shared__ char smraw[];
    __nv_bfloat16* Wb = (__nv_bfloat16*)smraw;                    // 128*128 bf16 = 32KB
    float* bs = (float*)(smraw + DD * DD * 2);                    // 128 f
    float* qs = bs + DD;                                          // 128 f
    __nv_bfloat16* zt = (__nv_bfloat16*)(qs + DD);                // 8 warps * 16*128 bf16 = 32KB
    float* scr = (float*)(zt + 8 * 16 * DD);                      // 8 warps * 256 f = 8KB
    __shared__ float red[8];

    const float* __restrict__ zin = g_z[p];
    int tid = threadIdx.x, lane = tid & 31, wid = tid >> 5;

    for (int i = tid; i < DD * DD; i += 256)
        Wb[i] = __float2bfloat16(W[i]);
    if (tid < DD) { bs[tid] = b[tid]; qs[tid] = q[tid]; }
    __syncthreads();

    float wsum_local = 0.f;
    int tile = blockIdx.x * 8 + wid;

    if (tile < ATT_TILES) {
        __nv_bfloat16* myz = zt + wid * (16 * DD);
        float* myscr = scr + wid * 256;

        #pragma unroll
        for (int j = 0; j < 16; j++) {
            int idx = j * 32 + lane;
            int row = idx >> 5, c4 = idx & 31;
            float4 v = *(const float4*)&zin[(size_t)(tile * 16 + row) * DD + c4 * 4];
            __nv_bfloat162* dst = (__nv_bfloat162*)&myz[row * DD + c4 * 4];
            dst[0] = __floats2bfloat162_rn(v.x, v.y);
            dst[1] = __floats2bfloat162_rn(v.z, v.w);
        }
        __syncwarp();

        wmma::fragment<wmma::accumulator, 16, 16, 16, float> accf[8];
        #pragma unroll
        for (int n = 0; n < 8; n++) wmma::fill_fragment(accf[n], 0.f);

        #pragma unroll
        for (int k = 0; k < 8; k++) {
            wmma::fragment<wmma::matrix_a, 16, 16, 16, __nv_bfloat16, wmma::row_major> af;
            wmma::load_matrix_sync(af, myz + k * 16, DD);
            #pragma unroll
            for (int n = 0; n < 8; n++) {
                wmma::fragment<wmma::matrix_b, 16, 16, 16, __nv_bfloat16, wmma::row_major> bfg;
                wmma::load_matrix_sync(bfg, Wb + (k * 16) * DD + n * 16, DD);
                wmma::mma_sync(accf[n], af, bfg, accf[n]);
            }
        }

        #pragma unroll
        for (int n = 0; n < 8; n++) {
            wmma::store_matrix_sync(myscr, accf[n], 16, wmma::mem_row_major);
            __syncwarp();
            #pragma unroll
            for (int i = 0; i < 8; i++) {
                int e = i * 32 + lane;
                int col = n * 16 + (e & 15);
                wsum_local += htanh(myscr[e] + bs[col]) * qs[col];
            }
            __syncwarp();
        }
    }

    #pragma unroll
    for (int off = 16; off > 0; off >>= 1)
        wsum_local += __shfl_xor_sync(0xffffffffu, wsum_local, off);
    if (lane == 0) red[wid] = wsum_local;
    __syncthreads();
    if (tid == 0) {
        float s = 0.f;
        #pragma unroll
        for (int i = 0; i < 8; i++) s += red[i];
        atomicAdd(&g_wsum[p], s);
    }
}

// ---------------- softmax(beta) + combine ----------------
__global__ void k_combine(float* __restrict__ out) {
    int idx = blockIdx.x * blockDim.x + threadIdx.x;
    if (idx < NN * DD / 4) {
        float w0 = g_wsum[0] / (float)NN;
        float w1 = g_wsum[1] / (float)NN;
        float m = fmaxf(w0, w1);
        float e0 = expf(w0 - m), e1 = expf(w1 - m);
        float inv = 1.f / (e0 + e1);
        float b0 = e0 * inv, b1 = e1 * inv;
        float4 z0 = ((const float4*)g_z[0])[idx];
        float4 z1 = ((const float4*)g_z[1])[idx];
        float4 o;
        o.x = b0 * z0.x + b1 * z1.x;
        o.y = b0 * z0.y + b1 * z1.y;
        o.z = b0 * z0.z + b1 * z1.z;
        o.w = b0 * z0.w + b1 * z1.w;
        ((float4*)out)[idx] = o;
    }
}

// ---------------- launch (R14 topology; k_scale removed) ----------------
extern "C" void kernel_launch(void* const* d_in, const int* in_sizes, int n_in,
                              void* d_out, int out_size) {
    const float* h     = (const float*)d_in[0];
    const int*   src0  = (const int*)d_in[1];
    const int*   dst0  = (const int*)d_in[2];
    const int*   src1  = (const int*)d_in[3];
    const int*   dst1  = (const int*)d_in[4];
    const float* W_h   = (const float*)d_in[5];
    const float* b_h   = (const float*)d_in[6];
    const float* W_att = (const float*)d_in[7];
    const float* b_att = (const float*)d_in[8];
    const float* q_att = (const float*)d_in[9];
    float* out = (float*)d_out;

    static cudaStream_t sB = nullptr, sC = nullptr;
    static cudaEvent_t evZ = nullptr, evLin = nullptr, evB = nullptr, evC = nullptr;
    static bool init_done = false;

    size_t smemGemm = (size_t)(DD * DD + DD + 8 * 8 * DD) * sizeof(float);
    size_t smemAtt  = (size_t)(DD * DD * 2) + (size_t)(2 * DD) * sizeof(float)
                    + (size_t)(8 * 16 * DD * 2) + (size_t)(8 * 256) * sizeof(float);

    if (!init_done) {
        cudaFuncSetAttribute(k_linear, cudaFuncAttributeMaxDynamicSharedMemorySize, (int)smemGemm);
        cudaFuncSetAttribute(k_att,    cudaFuncAttributeMaxDynamicSharedMemorySize, (int)smemAtt);
        cudaStreamCreateWithFlags(&sB, cudaStreamNonBlocking);
        cudaStreamCreateWithFlags(&sC, cudaStreamNonBlocking);
        cudaEventCreateWithFlags(&evZ, cudaEventDisableTiming);
        cudaEventCreateWithFlags(&evLin, cudaEventDisableTiming);
        cudaEventCreateWithFlags(&evB, cudaEventDisableTiming);
        cudaEventCreateWithFlags(&evC, cudaEventDisableTiming);
        init_done = true;
    }

    dim3 gE((EE + 255) / 256);
    dim3 gA(NN / 8);
    dim3 gAtt((ATT_TILES + 7) / 8);

    // ---- stream 0 (capture origin): linear first ----
    k_linear<<<304, 256, smemGemm>>>(h, W_h, b_h);
    cudaEventRecord(evLin, 0);

    // ---- stream B: zero, then graph 1 CSR chain ----
    k_zero<<<(NN + 255) / 256, 256, 0, sB>>>();
    cudaEventRecord(evZ, sB);

    k_count<<<gE, 256, 0, sB>>>(src1, dst1, 1);
    k_scan1<<<SNCH, SCH, 0, sB>>>(1);
    k_scan2<<<1, 32, 0, sB>>>(1);
    k_scan3<<<SNCH, SCH, 0, sB>>>(1);
    k_fill<<<gE, 256, 0, sB>>>(src1, dst1, 1);

    // ---- stream C: graph 0 CSR chain (waits only on zero) ----
    cudaStreamWaitEvent(sC, evZ, 0);
    k_count<<<gE, 256, 0, sC>>>(src0, dst0, 0);
    k_scan1<<<SNCH, SCH, 0, sC>>>(0);
    k_scan2<<<1, 32, 0, sC>>>(0);
    k_scan3<<<SNCH, SCH, 0, sC>>>(0);
    k_fill<<<gE, 256, 0, sC>>>(src0, dst0, 0);

    // ---- stream C: graph 0 propagation (needs linear) ----
    cudaStreamWaitEvent(sC, evLin, 0);
    k_agg<<<gA, 256, 0, sC>>>(0, 1, 1, 0);   // h1h -> xs[0][0]
    k_agg<<<gA, 256, 0, sC>>>(0, 0, 0, 0);   // xs[0][0] -> xs[0][1]
    k_agg<<<gA, 256, 0, sC>>>(0, 1, 0, 1);   // xs[0][1] -> z[0]
    k_att<<<gAtt, 256, smemAtt, sC>>>(W_att, b_att, q_att, 0);
    cudaEventRecord(evC, sC);

    // ---- stream B: graph 1 propagation (needs linear) ----
    cudaStreamWaitEvent(sB, evLin, 0);
    k_agg<<<gA, 256, 0, sB>>>(1, 1, 1, 0);   // h1h -> xs[1][0]
    k_agg<<<gA, 256, 0, sB>>>(1, 0, 0, 0);   // xs[1][0] -> xs[1][1]
    k_agg<<<gA, 256, 0, sB>>>(1, 1, 0, 1);   // xs[1][1] -> z[1]
    k_att<<<gAtt, 256, smemAtt, sB>>>(W_att, b_att, q_att, 1);
    cudaEventRecord(evB, sB);

    // ---- join + combine on origin ----
    cudaStreamWaitEvent(0, evB, 0);
    cudaStreamWaitEvent(0, evC, 0);
    k_combine<<<(NN * DD / 4 + 255) / 256, 256>>>(out);
}

// round 17
// speedup vs baseline: 1.1130x; 1.0212x over previous
#include <cuda_runtime.h>
#include <cuda_fp16.h>
#include <cuda_bf16.h>
#include <mma.h>
#include <math.h>

using namespace nvcuda;

#define NN 50000
#define EE 800000
#define DD 128
#define ALPHAv 0.1f
#define SCH 512
#define SNCH ((NN + SCH - 1) / SCH)   // 98

// ---------------- device scratch ----------------
__device__ __align__(16) __half g_h1h[NN * DD];                 // fp16 relu(h @ W_h + b)
__device__ __align__(16) __half g_xs[2][2][(NN + 1) * DD];      // propagated features; row NN = zero pad
__device__ __align__(16) __half g_z[2][NN * DD];                // final APPNP output per metapath (fp16)
__device__ int   g_deg_out[2][NN];
__device__ int   g_deg_in[2][NN];
__device__ float g_norm_s[2][NN];
__device__ float g_norm_d[2][NN];
__device__ int   g_rowoff[2][NN + 1];
__device__ int   g_cursor[2][NN];
__device__ int   g_csr_src[2][EE];
__device__ int   g_chsum[2][SNCH];
__device__ int   g_chbase[2][SNCH];
__device__ float g_wsum[2];

// ---------------- helpers ----------------
__device__ __forceinline__ float4 f4_fma(float s, float4 a, float4 b) {
    float4 r; r.x = s * a.x + b.x; r.y = s * a.y + b.y; r.z = s * a.z + b.z; r.w = s * a.w + b.w;
    return r;
}
__device__ __forceinline__ float htanh(float x) {
    float t;
    asm("tanh.approx.f32 %0, %1;" : "=f"(t) : "f"(x));
    return t;
}

// ---------------- zero / init ----------------
__global__ void k_zero() {
    int i = blockIdx.x * blockDim.x + threadIdx.x;
    if (i < NN) {
        g_deg_out[0][i] = 0; g_deg_out[1][i] = 0;
        g_deg_in[0][i]  = 0; g_deg_in[1][i]  = 0;
    }
    if (i < DD) {
        __half z = __float2half(0.f);
        g_xs[0][0][NN * DD + i] = z; g_xs[0][1][NN * DD + i] = z;
        g_xs[1][0][NN * DD + i] = z; g_xs[1][1][NN * DD + i] = z;
    }
    if (i < 2) g_wsum[i] = 0.f;
}

// ---------------- linear + relu -> fp16 only (fp32 copy was dead) ----------------
__global__ __launch_bounds__(256) void k_linear(const float* __restrict__ h,
                                                const float* __restrict__ W,
                                                const float* __restrict__ b) {
    extern __shared__ float sm[];
    float* Ws = sm;               // DD*DD
    float* bs = Ws + DD * DD;     // DD
    float* rows = bs + DD;        // 8 warps * 8 * DD

    int tid = threadIdx.x, lane = tid & 31, wid = tid >> 5;
    for (int i = tid; i < DD * DD / 4; i += blockDim.x)
        ((float4*)Ws)[i] = ((const float4*)W)[i];
    if (tid < DD) bs[tid] = b[tid];
    __syncthreads();

    float* myrows = rows + wid * (8 * DD);
    float4 bf = *(float4*)&bs[lane * 4];
    int gw = blockIdx.x * 8 + wid;
    int nwarps = gridDim.x * 8;
    const int NT = NN / 8;   // 6250, exact

    for (int tile = gw; tile < NT; tile += nwarps) {
        __syncwarp();
        #pragma unroll
        for (int r = 0; r < 8; r++)
            *(float4*)&myrows[r * DD + lane * 4] =
                *(const float4*)&h[(size_t)(tile * 8 + r) * DD + lane * 4];
        __syncwarp();

        float4 acc[8];
        #pragma unroll
        for (int r = 0; r < 8; r++) acc[r] = bf;

        #pragma unroll 8
        for (int k = 0; k < DD; k += 4) {
            float4 w0 = *(float4*)&Ws[(k + 0) * DD + lane * 4];
            float4 w1 = *(float4*)&Ws[(k + 1) * DD + lane * 4];
            float4 w2 = *(float4*)&Ws[(k + 2) * DD + lane * 4];
            float4 w3 = *(float4*)&Ws[(k + 3) * DD + lane * 4];
            #pragma unroll
            for (int r = 0; r < 8; r++) {
                float4 hv = *(float4*)&myrows[r * DD + k];
                acc[r] = f4_fma(hv.x, w0, acc[r]);
                acc[r] = f4_fma(hv.y, w1, acc[r]);
                acc[r] = f4_fma(hv.z, w2, acc[r]);
                acc[r] = f4_fma(hv.w, w3, acc[r]);
            }
        }
        #pragma unroll
        for (int r = 0; r < 8; r++) {
            float ox = fmaxf(acc[r].x, 0.f), oy = fmaxf(acc[r].y, 0.f);
            float oz = fmaxf(acc[r].z, 0.f), ow = fmaxf(acc[r].w, 0.f);
            size_t off = (size_t)(tile * 8 + r) * DD + lane * 4;
            __half2 p0 = __floats2half2_rn(ox, oy);
            __half2 p1 = __floats2half2_rn(oz, ow);
            uint2 hw; hw.x = *(unsigned*)&p0; hw.y = *(unsigned*)&p1;
            *(uint2*)&g_h1h[off] = hw;
        }
    }
}

// ---------------- degree count (per graph, scalar) ----------------
__global__ void k_count(const int* __restrict__ s, const int* __restrict__ d, int g) {
    int e = blockIdx.x * blockDim.x + threadIdx.x;
    if (e < EE) {
        atomicAdd(&g_deg_out[g][s[e]], 1);
        atomicAdd(&g_deg_in[g][d[e]], 1);
    }
}

// ---------------- scan1 + norms fused (per graph) ----------------
__global__ __launch_bounds__(SCH) void k_scan1(int g) {
    int c = blockIdx.x;
    int i = c * SCH + threadIdx.x;
    int v = 0;
    if (i < NN) {
        v = g_deg_in[g][i];
        int dout = g_deg_out[g][i]; if (dout < 1) dout = 1;
        int din = v < 1 ? 1 : v;
        g_norm_s[g][i] = rsqrtf((float)dout);
        g_norm_d[g][i] = rsqrtf((float)din);
    }
    __shared__ int ws[16];
    int lane = threadIdx.x & 31, wid = threadIdx.x >> 5;
    int sum = v;
    #pragma unroll
    for (int off = 16; off > 0; off >>= 1)
        sum += __shfl_xor_sync(0xffffffffu, sum, off);
    if (lane == 0) ws[wid] = sum;
    __syncthreads();
    if (wid == 0) {
        int s = (lane < 16) ? ws[lane] : 0;
        #pragma unroll
        for (int off = 8; off > 0; off >>= 1)
            s += __shfl_xor_sync(0xffffffffu, s, off);
        if (lane == 0) g_chsum[g][c] = s;
    }
}

__global__ void k_scan2(int g) {   // 1 warp
    int lane = threadIdx.x & 31;
    int carry = 0;
    for (int base = 0; base < SNCH; base += 32) {
        int idx = base + lane;
        int v = (idx < SNCH) ? g_chsum[g][idx] : 0;
        int x = v;
        #pragma unroll
        for (int off = 1; off < 32; off <<= 1) {
            int t = __shfl_up_sync(0xffffffffu, x, off);
            if (lane >= off) x += t;
        }
        if (idx < SNCH) g_chbase[g][idx] = carry + x - v;
        carry += __shfl_sync(0xffffffffu, x, 31);
    }
    if (lane == 0) g_rowoff[g][NN] = carry;   // == EE
}

__global__ __launch_bounds__(SCH) void k_scan3(int g) {
    int c = blockIdx.x;
    int i = c * SCH + threadIdx.x;
    int v = (i < NN) ? g_deg_in[g][i] : 0;
    __shared__ int ws[16];
    int lane = threadIdx.x & 31, wid = threadIdx.x >> 5;
    int x = v;
    #pragma unroll
    for (int off = 1; off < 32; off <<= 1) {
        int t = __shfl_up_sync(0xffffffffu, x, off);
        if (lane >= off) x += t;
    }
    if (lane == 31) ws[wid] = x;
    __syncthreads();
    if (wid == 0) {
        int y = (lane < 16) ? ws[lane] : 0;
        #pragma unroll
        for (int off = 1; off < 32; off <<= 1) {
            int t = __shfl_up_sync(0xffffffffu, y, off);
            if (lane >= off) y += t;
        }
        if (lane < 16) ws[lane] = y;
    }
    __syncthreads();
    int wb = wid ? ws[wid - 1] : 0;
    int excl = g_chbase[g][c] + wb + x - v;
    if (i < NN) { g_rowoff[g][i] = excl; g_cursor[g][i] = excl; }
}

// ---------------- fill CSR (per graph, scalar) ----------------
__global__ void k_fill(const int* __restrict__ s, const int* __restrict__ d, int g) {
    int e = blockIdx.x * blockDim.x + threadIdx.x;
    if (e < EE) {
        int slot = atomicAdd(&g_cursor[g][d[e]], 1);
        g_csr_src[g][slot] = s[e];
    }
}

// ---------------- APPNP aggregation: warp per dst node, float4 paired-row gathers ----------------
// first=1: gather h1h and apply norm_s[src] in fp32 (replaces k_scale entirely).
__global__ __launch_bounds__(256) void k_agg(int g, int pp, int first, int last) {
    int lane = threadIdx.x & 31, wid = threadIdx.x >> 5;
    int node = blockIdx.x * 8 + wid;
    if (node >= NN) return;

    const __half* __restrict__ xin = first ? g_h1h : g_xs[g][pp];
    const int* __restrict__ csr = g_csr_src[g];
    const float* __restrict__ nsrc = g_norm_s[g];
    int ro = g_rowoff[g][node], re = g_rowoff[g][node + 1];

    int half_ = lane >> 4;          // which row of each pair this lane loads
    int sub = lane & 15;            // 16-byte column slice

    float acc[8];
    #pragma unroll
    for (int i = 0; i < 8; i++) acc[i] = 0.f;

    if (first) {
        for (int base = ro; base < re; base += 32) {
            int e = base + lane;
            int s = (e < re) ? csr[e] : 0;                // pad -> row 0 (valid data)
            float nm = (e < re) ? nsrc[s] : 0.f;          // pad -> weight 0
            int cnt = re - base; if (cnt > 32) cnt = 32;
            int cr = (cnt + 7) & ~7;
            for (int j = 0; j < cr; j += 8) {
                int rsel[4]; float msel[4];
                #pragma unroll
                for (int k2 = 0; k2 < 4; k2++) {
                    int rA = __shfl_sync(0xffffffffu, s, j + 2 * k2);
                    int rB = __shfl_sync(0xffffffffu, s, j + 2 * k2 + 1);
                    float mA = __shfl_sync(0xffffffffu, nm, j + 2 * k2);
                    float mB = __shfl_sync(0xffffffffu, nm, j + 2 * k2 + 1);
                    rsel[k2] = half_ ? rB : rA;
                    msel[k2] = half_ ? mB : mA;
                }
                uint4 v[4];
                #pragma unroll
                for (int k2 = 0; k2 < 4; k2++)
                    v[k2] = *(const uint4*)&xin[(size_t)rsel[k2] * DD + sub * 8];
                #pragma unroll
                for (int k2 = 0; k2 < 4; k2++) {
                    float m = msel[k2];
                    float2 f0 = __half22float2(*(__half2*)&v[k2].x);
                    float2 f1 = __half22float2(*(__half2*)&v[k2].y);
                    float2 f2 = __half22float2(*(__half2*)&v[k2].z);
                    float2 f3 = __half22float2(*(__half2*)&v[k2].w);
                    acc[0] = fmaf(f0.x, m, acc[0]); acc[1] = fmaf(f0.y, m, acc[1]);
                    acc[2] = fmaf(f1.x, m, acc[2]); acc[3] = fmaf(f1.y, m, acc[3]);
                    acc[4] = fmaf(f2.x, m, acc[4]); acc[5] = fmaf(f2.y, m, acc[5]);
                    acc[6] = fmaf(f3.x, m, acc[6]); acc[7] = fmaf(f3.y, m, acc[7]);
                }
            }
        }
    } else {
        for (int base = ro; base < re; base += 32) {
            int e = base + lane;
            int s = (e < re) ? csr[e] : NN;      // NN = zero pad row
            int cnt = re - base; if (cnt > 32) cnt = 32;
            int cr = (cnt + 7) & ~7;
            for (int j = 0; j < cr; j += 8) {
                int rsel[4];
                #pragma unroll
                for (int k2 = 0; k2 < 4; k2++) {
                    int rA = __shfl_sync(0xffffffffu, s, j + 2 * k2);
                    int rB = __shfl_sync(0xffffffffu, s, j + 2 * k2 + 1);
                    rsel[k2] = half_ ? rB : rA;
                }
                uint4 v[4];
                #pragma unroll
                for (int k2 = 0; k2 < 4; k2++)
                    v[k2] = *(const uint4*)&xin[(size_t)rsel[k2] * DD + sub * 8];
                #pragma unroll
                for (int k2 = 0; k2 < 4; k2++) {
                    float2 f0 = __half22float2(*(__half2*)&v[k2].x);
                    float2 f1 = __half22float2(*(__half2*)&v[k2].y);
                    float2 f2 = __half22float2(*(__half2*)&v[k2].z);
                    float2 f3 = __half22float2(*(__half2*)&v[k2].w);
                    acc[0] += f0.x; acc[1] += f0.y; acc[2] += f1.x; acc[3] += f1.y;
                    acc[4] += f2.x; acc[5] += f2.y; acc[6] += f3.x; acc[7] += f3.y;
                }
            }
        }
    }

    #pragma unroll
    for (int i = 0; i < 8; i++)
        acc[i] += __shfl_xor_sync(0xffffffffu, acc[i], 16);

    float c = (1.f - ALPHAv) * g_norm_d[g][node];
    uint4 h0raw = *(const uint4*)&g_h1h[(size_t)node * DD + sub * 8];
    float2 h0a = __half22float2(*(__half2*)&h0raw.x);
    float2 h0b = __half22float2(*(__half2*)&h0raw.y);
    float2 h0c = __half22float2(*(__half2*)&h0raw.z);
    float2 h0d = __half22float2(*(__half2*)&h0raw.w);
    float v8[8];
    v8[0] = c * acc[0] + ALPHAv * h0a.x; v8[1] = c * acc[1] + ALPHAv * h0a.y;
    v8[2] = c * acc[2] + ALPHAv * h0b.x; v8[3] = c * acc[3] + ALPHAv * h0b.y;
    v8[4] = c * acc[4] + ALPHAv * h0c.x; v8[5] = c * acc[5] + ALPHAv * h0c.y;
    v8[6] = c * acc[6] + ALPHAv * h0d.x; v8[7] = c * acc[7] + ALPHAv * h0d.y;

    if (last) {
        __half2 o0 = __floats2half2_rn(v8[half_ * 4 + 0], v8[half_ * 4 + 1]);
        __half2 o1 = __floats2half2_rn(v8[half_ * 4 + 2], v8[half_ * 4 + 3]);
        uint2 w; w.x = *(unsigned*)&o0; w.y = *(unsigned*)&o1;
        *(uint2*)&g_z[g][(size_t)node * DD + sub * 8 + half_ * 4] = w;
    } else {
        float ns = g_norm_s[g][node];
        __half2 o0 = __floats2half2_rn(v8[half_ * 4 + 0] * ns, v8[half_ * 4 + 1] * ns);
        __half2 o1 = __floats2half2_rn(v8[half_ * 4 + 2] * ns, v8[half_ * 4 + 3] * ns);
        uint2 w; w.x = *(unsigned*)&o0; w.y = *(unsigned*)&o1;
        *(uint2*)&g_xs[g][1 - pp][(size_t)node * DD + sub * 8 + half_ * 4] = w;
    }
}

// ---------------- attention scores via bf16 WMMA tensor cores (per graph; z fp16) ----------------
#define ATT_TILES (NN / 16)   // 3125, exact

__global__ __launch_bounds__(256) void k_att(const float* __restrict__ W,
                                             const float* __restrict__ b,
                                             const float* __restrict__ q, int p) {
    extern __shared__ char smraw[];
    __nv_bfloat16* Wb = (__nv_bfloat16*)smraw;                    // 128*128 bf16 = 32KB
    float* bs = (float*)(smraw + DD * DD * 2);                    // 128 f
    float* qs = bs + DD;                                          // 128 f
    __nv_bfloat16* zt = (__nv_bfloat16*)(qs + DD);                // 8 warps * 16*128 bf16 = 32KB
    float* scr = (float*)(zt + 8 * 16 * DD);                      // 8 warps * 256 f = 8KB
    __shared__ float red[8];

    const __half* __restrict__ zin = g_z[p];
    int tid = threadIdx.x, lane = tid & 31, wid = tid >> 5;

    for (int i = tid; i < DD * DD; i += 256)
        Wb[i] = __float2bfloat16(W[i]);
    if (tid < DD) { bs[tid] = b[tid]; qs[tid] = q[tid]; }
    __syncthreads();

    float wsum_local = 0.f;
    int tile = blockIdx.x * 8 + wid;

    if (tile < ATT_TILES) {
        __nv_bfloat16* myz = zt + wid * (16 * DD);
        float* myscr = scr + wid * 256;

        // load 16x128 fp16 rows -> bf16 smem (8 uint4 loads per lane)
        #pragma unroll
        for (int j = 0; j < 8; j++) {
            int idx = j * 32 + lane;          // 256 uint4 groups: 16 rows * 16 per row
            int row = idx >> 4, c8 = idx & 15;
            uint4 v = *(const uint4*)&zin[(size_t)(tile * 16 + row) * DD + c8 * 8];
            float2 f0 = __half22float2(*(__half2*)&v.x);
            float2 f1 = __half22float2(*(__half2*)&v.y);
            float2 f2 = __half22float2(*(__half2*)&v.z);
            float2 f3 = __half22float2(*(__half2*)&v.w);
            __nv_bfloat162* dst = (__nv_bfloat162*)&myz[row * DD + c8 * 8];
            dst[0] = __floats2bfloat162_rn(f0.x, f0.y);
            dst[1] = __floats2bfloat162_rn(f1.x, f1.y);
            dst[2] = __floats2bfloat162_rn(f2.x, f2.y);
            dst[3] = __floats2bfloat162_rn(f3.x, f3.y);
        }
        __syncwarp();

        wmma::fragment<wmma::accumulator, 16, 16, 16, float> accf[8];
        #pragma unroll
        for (int n = 0; n < 8; n++) wmma::fill_fragment(accf[n], 0.f);

        #pragma unroll
        for (int k = 0; k < 8; k++) {
            wmma::fragment<wmma::matrix_a, 16, 16, 16, __nv_bfloat16, wmma::row_major> af;
            wmma::load_matrix_sync(af, myz + k * 16, DD);
            #pragma unroll
            for (int n = 0; n < 8; n++) {
                wmma::fragment<wmma::matrix_b, 16, 16, 16, __nv_bfloat16, wmma::row_major> bfg;
                wmma::load_matrix_sync(bfg, Wb + (k * 16) * DD + n * 16, DD);
                wmma::mma_sync(accf[n], af, bfg, accf[n]);
            }
        }

        #pragma unroll
        for (int n = 0; n < 8; n++) {
            wmma::store_matrix_sync(myscr, accf[n], 16, wmma::mem_row_major);
            __syncwarp();
            #pragma unroll
            for (int i = 0; i < 8; i++) {
                int e = i * 32 + lane;
                int col = n * 16 + (e & 15);
                wsum_local += htanh(myscr[e] + bs[col]) * qs[col];
            }
            __syncwarp();
        }
    }

    #pragma unroll
    for (int off = 16; off > 0; off >>= 1)
        wsum_local += __shfl_xor_sync(0xffffffffu, wsum_local, off);
    if (lane == 0) red[wid] = wsum_local;
    __syncthreads();
    if (tid == 0) {
        float s = 0.f;
        #pragma unroll
        for (int i = 0; i < 8; i++) s += red[i];
        atomicAdd(&g_wsum[p], s);
    }
}

// ---------------- softmax(beta) + combine (z fp16 -> out fp32) ----------------
__global__ void k_combine(float* __restrict__ out) {
    int idx = blockIdx.x * blockDim.x + threadIdx.x;   // 8-element groups
    if (idx < NN * DD / 8) {
        float w0 = g_wsum[0] / (float)NN;
        float w1 = g_wsum[1] / (float)NN;
        float m = fmaxf(w0, w1);
        float e0 = expf(w0 - m), e1 = expf(w1 - m);
        float inv = 1.f / (e0 + e1);
        float b0 = e0 * inv, b1 = e1 * inv;
        uint4 r0 = *(const uint4*)&g_z[0][(size_t)idx * 8];
        uint4 r1 = *(const uint4*)&g_z[1][(size_t)idx * 8];
        float4 oA, oB;
        float2 a0 = __half22float2(*(__half2*)&r0.x), c0 = __half22float2(*(__half2*)&r1.x);
        float2 a1 = __half22float2(*(__half2*)&r0.y), c1 = __half22float2(*(__half2*)&r1.y);
        float2 a2 = __half22float2(*(__half2*)&r0.z), c2 = __half22float2(*(__half2*)&r1.z);
        float2 a3 = __half22float2(*(__half2*)&r0.w), c3 = __half22float2(*(__half2*)&r1.w);
        oA.x = b0 * a0.x + b1 * c0.x; oA.y = b0 * a0.y + b1 * c0.y;
        oA.z = b0 * a1.x + b1 * c1.x; oA.w = b0 * a1.y + b1 * c1.y;
        oB.x = b0 * a2.x + b1 * c2.x; oB.y = b0 * a2.y + b1 * c2.y;
        oB.z = b0 * a3.x + b1 * c3.x; oB.w = b0 * a3.y + b1 * c3.y;
        *(float4*)&out[(size_t)idx * 8]     = oA;
        *(float4*)&out[(size_t)idx * 8 + 4] = oB;
    }
}

// ---------------- launch (R16 topology, verbatim) ----------------
extern "C" void kernel_launch(void* const* d_in, const int* in_sizes, int n_in,
                              void* d_out, int out_size) {
    const float* h     = (const float*)d_in[0];
    const int*   src0  = (const int*)d_in[1];
    const int*   dst0  = (const int*)d_in[2];
    const int*   src1  = (const int*)d_in[3];
    const int*   dst1  = (const int*)d_in[4];
    const float* W_h   = (const float*)d_in[5];
    const float* b_h   = (const float*)d_in[6];
    const float* W_att = (const float*)d_in[7];
    const float* b_att = (const float*)d_in[8];
    const float* q_att = (const float*)d_in[9];
    float* out = (float*)d_out;

    static cudaStream_t sB = nullptr, sC = nullptr;
    static cudaEvent_t evZ = nullptr, evLin = nullptr, evB = nullptr, evC = nullptr;
    static bool init_done = false;

    size_t smemGemm = (size_t)(DD * DD + DD + 8 * 8 * DD) * sizeof(float);
    size_t smemAtt  = (size_t)(DD * DD * 2) + (size_t)(2 * DD) * sizeof(float)
                    + (size_t)(8 * 16 * DD * 2) + (size_t)(8 * 256) * sizeof(float);

    if (!init_done) {
        cudaFuncSetAttribute(k_linear, cudaFuncAttributeMaxDynamicSharedMemorySize, (int)smemGemm);
        cudaFuncSetAttribute(k_att,    cudaFuncAttributeMaxDynamicSharedMemorySize, (int)smemAtt);
        cudaStreamCreateWithFlags(&sB, cudaStreamNonBlocking);
        cudaStreamCreateWithFlags(&sC, cudaStreamNonBlocking);
        cudaEventCreateWithFlags(&evZ, cudaEventDisableTiming);
        cudaEventCreateWithFlags(&evLin, cudaEventDisableTiming);
        cudaEventCreateWithFlags(&evB, cudaEventDisableTiming);
        cudaEventCreateWithFlags(&evC, cudaEventDisableTiming);
        init_done = true;
    }

    dim3 gE((EE + 255) / 256);
    dim3 gA(NN / 8);
    dim3 gAtt((ATT_TILES + 7) / 8);

    // ---- stream 0 (capture origin): linear first ----
    k_linear<<<304, 256, smemGemm>>>(h, W_h, b_h);
    cudaEventRecord(evLin, 0);

    // ---- stream B: zero, then graph 1 CSR chain ----
    k_zero<<<(NN + 255) / 256, 256, 0, sB>>>();
    cudaEventRecord(evZ, sB);

    k_count<<<gE, 256, 0, sB>>>(src1, dst1, 1);
    k_scan1<<<SNCH, SCH, 0, sB>>>(1);
    k_scan2<<<1, 32, 0, sB>>>(1);
    k_scan3<<<SNCH, SCH, 0, sB>>>(1);
    k_fill<<<gE, 256, 0, sB>>>(src1, dst1, 1);

    // ---- stream C: graph 0 CSR chain (waits only on zero) ----
    cudaStreamWaitEvent(sC, evZ, 0);
    k_count<<<gE, 256, 0, sC>>>(src0, dst0, 0);
    k_scan1<<<SNCH, SCH, 0, sC>>>(0);
    k_scan2<<<1, 32, 0, sC>>>(0);
    k_scan3<<<SNCH, SCH, 0, sC>>>(0);
    k_fill<<<gE, 256, 0, sC>>>(src0, dst0, 0);

    // ---- stream C: graph 0 propagation (needs linear) ----
    cudaStreamWaitEvent(sC, evLin, 0);
    k_agg<<<gA, 256, 0, sC>>>(0, 1, 1, 0);   // h1h -> xs[0][0]
    k_agg<<<gA, 256, 0, sC>>>(0, 0, 0, 0);   // xs[0][0] -> xs[0][1]
    k_agg<<<gA, 256, 0, sC>>>(0, 1, 0, 1);   // xs[0][1] -> z[0]
    k_att<<<gAtt, 256, smemAtt, sC>>>(W_att, b_att, q_att, 0);
    cudaEventRecord(evC, sC);

    // ---- stream B: graph 1 propagation (needs linear) ----
    cudaStreamWaitEvent(sB, evLin, 0);
    k_agg<<<gA, 256, 0, sB>>>(1, 1, 1, 0);   // h1h -> xs[1][0]
    k_agg<<<gA, 256, 0, sB>>>(1, 0, 0, 0);   // xs[1][0] -> xs[1][1]
    k_agg<<<gA, 256, 0, sB>>>(1, 1, 0, 1);   // xs[1][1] -> z[1]
    k_att<<<gAtt, 256, smemAtt, sB>>>(W_att, b_att, q_att, 1);
    cudaEventRecord(evB, sB);

    // ---- join + combine on origin ----
    cudaStreamWaitEvent(0, evB, 0);
    cudaStreamWaitEvent(0, evC, 0);
    k_combine<<<(NN * DD / 8 + 255) / 256, 256>>>(out);
}